// round 1
// baseline (speedup 1.0000x reference)
#include <cuda_runtime.h>
#include <math.h>

// ---------------- problem constants ----------------
#define N_NODES  100000
#define N_EDGES  1600000
#define E_TOT    (N_EDGES + N_NODES)   // edges + self loops
#define F_IN     128
#define HC       128                   // HEADS*HID
#define HEADS    4
#define HID      32
#define OUT_CH   32
#define NEG_SLOPE 0.2f

// ---------------- scratch (device globals; no allocation allowed) -------
__device__ float g_h1  [N_NODES * HC];      // 51.2 MB  h1 = x @ W1
__device__ float g_h2in[N_NODES * HC];      // 51.2 MB  elu(agg1 + b1)
__device__ float g_h2  [N_NODES * OUT_CH];  // 12.8 MB  h2 = h2in @ W2
__device__ float g_aS1 [N_NODES * 4];
__device__ float g_aD1 [N_NODES * 4];
__device__ float g_aS2 [N_NODES];
__device__ float g_aD2 [N_NODES];
__device__ int   g_deg [N_NODES];
__device__ int   g_off [N_NODES + 1];
__device__ int   g_cursor[N_NODES];
__device__ int   g_csr [E_TOT];             // src node per dst-sorted edge
__device__ int   g_bsum[128];
__device__ int   g_is64;

// ---------------- edge dtype detection (int64 vs int32) -----------------
__global__ void k_detect(const int* __restrict__ w) {
    __shared__ int flag;
    if (threadIdx.x == 0) flag = 0;
    __syncthreads();
    int any = 0;
    for (int i = threadIdx.x; i < 2048; i += 256) any |= w[2 * i + 1];
    if (any) atomicOr(&flag, 1);
    __syncthreads();
    if (threadIdx.x == 0) g_is64 = (flag == 0) ? 1 : 0;
}

__device__ __forceinline__ int edge_at(const void* e, long long idx) {
    return g_is64 ? (int)((const long long*)e)[idx] : ((const int*)e)[idx];
}

// ---------------- CSR build ----------------
__global__ void k_zero() {
    int i = blockIdx.x * blockDim.x + threadIdx.x;
    if (i < N_NODES) g_deg[i] = 0;
}

__global__ void k_count(const void* __restrict__ e) {
    int t = blockIdx.x * blockDim.x + threadIdx.x;
    if (t >= E_TOT) return;
    int dst = (t < N_EDGES) ? edge_at(e, (long long)N_EDGES + t) : (t - N_EDGES);
    atomicAdd(&g_deg[dst], 1);
}

// per-block inclusive scan of g_deg -> g_off (block-local), totals -> g_bsum
__global__ void __launch_bounds__(1024) k_scan1() {
    __shared__ int wsum[32];
    int t = threadIdx.x, b = blockIdx.x;
    int i = b * 1024 + t;
    int v = (i < N_NODES) ? g_deg[i] : 0;
    int lane = t & 31, w = t >> 5;
    int s = v;
#pragma unroll
    for (int o = 1; o < 32; o <<= 1) { int u = __shfl_up_sync(~0u, s, o); if (lane >= o) s += u; }
    if (lane == 31) wsum[w] = s;
    __syncthreads();
    if (w == 0) {
        int xx = wsum[lane];
#pragma unroll
        for (int o = 1; o < 32; o <<= 1) { int u = __shfl_up_sync(~0u, xx, o); if (lane >= o) xx += u; }
        wsum[lane] = xx;
    }
    __syncthreads();
    int incl = s + (w ? wsum[w - 1] : 0);
    if (i < N_NODES) g_off[i] = incl;
    if (t == 1023) g_bsum[b] = incl;
}

// scan of 98 block totals -> exclusive
__global__ void __launch_bounds__(1024) k_scan2() {
    const int NB = (N_NODES + 1023) / 1024;  // 98
    __shared__ int wsum[32];
    int t = threadIdx.x;
    int v = (t < NB) ? g_bsum[t] : 0;
    int lane = t & 31, w = t >> 5;
    int s = v;
#pragma unroll
    for (int o = 1; o < 32; o <<= 1) { int u = __shfl_up_sync(~0u, s, o); if (lane >= o) s += u; }
    if (lane == 31) wsum[w] = s;
    __syncthreads();
    if (w == 0) {
        int xx = wsum[lane];
#pragma unroll
        for (int o = 1; o < 32; o <<= 1) { int u = __shfl_up_sync(~0u, xx, o); if (lane >= o) xx += u; }
        wsum[lane] = xx;
    }
    __syncthreads();
    int incl = s + (w ? wsum[w - 1] : 0);
    if (t < NB) g_bsum[t] = incl - v;  // exclusive
}

__global__ void k_scan3() {
    int i = blockIdx.x * blockDim.x + threadIdx.x;
    if (i >= N_NODES) return;
    int incl = g_off[i] + g_bsum[i >> 10];
    int excl = incl - g_deg[i];
    g_off[i]    = excl;
    g_cursor[i] = excl;
    if (i == N_NODES - 1) g_off[N_NODES] = incl;
}

__global__ void k_scatter(const void* __restrict__ e) {
    int t = blockIdx.x * blockDim.x + threadIdx.x;
    if (t >= E_TOT) return;
    int s, d;
    if (t < N_EDGES) { s = edge_at(e, t); d = edge_at(e, (long long)N_EDGES + t); }
    else             { s = d = t - N_EDGES; }
    int pos = atomicAdd(&g_cursor[d], 1);
    g_csr[pos] = s;
}

// ---------------- GEMM: Y[r, 0:BN] = X[r, 0:128] @ W[128, BN] -----------
// 256 threads; W fully staged in dynamic smem; A rows streamed via L1.
template <int BN, int TX, int NPT>
__global__ void __launch_bounds__(256) k_gemm(const float* __restrict__ X,
                                              const float* __restrict__ Wg,
                                              float* __restrict__ Y, int nrows) {
    extern __shared__ float ws[];
    const int K = 128;
    int tid = threadIdx.x;
    for (int i = tid * 4; i < K * BN; i += 1024)
        *(float4*)(ws + i) = *(const float4*)(Wg + i);
    __syncthreads();

    const int TY = 256 / TX;
    const int BM = TY * NPT;
    int tx = tid % TX, ty = tid / TX;
    long long row0 = (long long)blockIdx.x * BM + (long long)ty * NPT;

    float acc[NPT][8];
#pragma unroll
    for (int i = 0; i < NPT; i++)
#pragma unroll
        for (int j = 0; j < 8; j++) acc[i][j] = 0.f;

#pragma unroll 1
    for (int k = 0; k < K; k += 4) {
        float4 xa[NPT];
#pragma unroll
        for (int i = 0; i < NPT; i++) {
            long long r = row0 + i;
            xa[i] = (r < nrows) ? *(const float4*)(X + r * K + k)
                                : make_float4(0.f, 0.f, 0.f, 0.f);
        }
#pragma unroll
        for (int kk = 0; kk < 4; kk++) {
            float4 b0 = *(const float4*)(ws + (k + kk) * BN + tx * 8);
            float4 b1 = *(const float4*)(ws + (k + kk) * BN + tx * 8 + 4);
#pragma unroll
            for (int i = 0; i < NPT; i++) {
                float a = (kk == 0) ? xa[i].x : (kk == 1) ? xa[i].y : (kk == 2) ? xa[i].z : xa[i].w;
                acc[i][0] += a * b0.x; acc[i][1] += a * b0.y;
                acc[i][2] += a * b0.z; acc[i][3] += a * b0.w;
                acc[i][4] += a * b1.x; acc[i][5] += a * b1.y;
                acc[i][6] += a * b1.z; acc[i][7] += a * b1.w;
            }
        }
    }
#pragma unroll
    for (int i = 0; i < NPT; i++) {
        long long r = row0 + i;
        if (r < nrows) {
            *(float4*)(Y + r * BN + tx * 8)     = make_float4(acc[i][0], acc[i][1], acc[i][2], acc[i][3]);
            *(float4*)(Y + r * BN + tx * 8 + 4) = make_float4(acc[i][4], acc[i][5], acc[i][6], acc[i][7]);
        }
    }
}

// ---------------- attention coefficients --------------------------------
__global__ void __launch_bounds__(256) k_alpha1(const float* __restrict__ asw,
                                                const float* __restrict__ adw) {
    int gw = (blockIdx.x * 256 + threadIdx.x) >> 5;
    if (gw >= N_NODES) return;
    int lane = threadIdx.x & 31;
    float s[4], d[4];
#pragma unroll
    for (int h = 0; h < 4; h++) {
        float v = g_h1[gw * HC + h * 32 + lane];
        s[h] = v * __ldg(asw + h * 32 + lane);
        d[h] = v * __ldg(adw + h * 32 + lane);
    }
#pragma unroll
    for (int o = 16; o; o >>= 1) {
#pragma unroll
        for (int h = 0; h < 4; h++) {
            s[h] += __shfl_xor_sync(~0u, s[h], o);
            d[h] += __shfl_xor_sync(~0u, d[h], o);
        }
    }
    if (lane == 0) {
#pragma unroll
        for (int h = 0; h < 4; h++) { g_aS1[gw * 4 + h] = s[h]; g_aD1[gw * 4 + h] = d[h]; }
    }
}

__global__ void __launch_bounds__(256) k_alpha2(const float* __restrict__ asw,
                                                const float* __restrict__ adw) {
    int gw = (blockIdx.x * 256 + threadIdx.x) >> 5;
    if (gw >= N_NODES) return;
    int lane = threadIdx.x & 31;
    float v = g_h2[gw * OUT_CH + lane];
    float s = v * __ldg(asw + lane);
    float d = v * __ldg(adw + lane);
#pragma unroll
    for (int o = 16; o; o >>= 1) {
        s += __shfl_xor_sync(~0u, s, o);
        d += __shfl_xor_sync(~0u, d, o);
    }
    if (lane == 0) { g_aS2[gw] = s; g_aD2[gw] = d; }
}

// ---------------- GAT layer 1: softmax + aggregate (warp per node) ------
__global__ void __launch_bounds__(256) k_gat1(const float* __restrict__ b1) {
    int gw = (blockIdx.x * 256 + threadIdx.x) >> 5;
    if (gw >= N_NODES) return;
    int lane = threadIdx.x & 31;
    int beg = g_off[gw], end = g_off[gw + 1];

    float4 aD4 = *(const float4*)&g_aD1[gw * 4];
    float aD[4] = {aD4.x, aD4.y, aD4.z, aD4.w};

    float m[4], ss[4];
#pragma unroll
    for (int h = 0; h < 4; h++) { m[h] = -1e30f; ss[h] = 0.f; }

    // pass 1: fused online max+sum (lane-strided edges)
    for (int e = beg + lane; e < end; e += 32) {
        int s = g_csr[e];
        float4 a4 = *(const float4*)&g_aS1[s * 4];
        float lg[4] = {a4.x + aD[0], a4.y + aD[1], a4.z + aD[2], a4.w + aD[3]};
#pragma unroll
        for (int h = 0; h < 4; h++) {
            float l = lg[h]; l = fmaxf(l, NEG_SLOPE * l);
            float nm = fmaxf(m[h], l);
            ss[h] = ss[h] * __expf(m[h] - nm) + __expf(l - nm);
            m[h] = nm;
        }
    }
    // warp combine (all lanes end with full result)
#pragma unroll
    for (int o = 16; o; o >>= 1) {
#pragma unroll
        for (int h = 0; h < 4; h++) {
            float om = __shfl_xor_sync(~0u, m[h], o);
            float os = __shfl_xor_sync(~0u, ss[h], o);
            float nm = fmaxf(m[h], om);
            ss[h] = ss[h] * __expf(m[h] - nm) + os * __expf(om - nm);
            m[h] = nm;
        }
    }

    // pass 2: weighted aggregation; lane owns channels [4*lane, 4*lane+4)
    int head = lane >> 3;
    int c4 = lane * 4;
    float mh = m[head], inv = 1.f / ss[head], aDh = aD[head];
    float4 acc = make_float4(0.f, 0.f, 0.f, 0.f);
    for (int e = beg; e < end; e++) {
        int s = g_csr[e];                       // broadcast load
        float av = g_aS1[s * 4 + head];
        float l = av + aDh; l = fmaxf(l, NEG_SLOPE * l);
        float w = __expf(l - mh) * inv;
        float4 v = *(const float4*)&g_h1[(long long)s * HC + c4];
        acc.x += w * v.x; acc.y += w * v.y; acc.z += w * v.z; acc.w += w * v.w;
    }
    float4 bb = *(const float4*)&b1[c4];
    float4 o;
    o.x = acc.x + bb.x; o.y = acc.y + bb.y; o.z = acc.z + bb.z; o.w = acc.w + bb.w;
    o.x = (o.x > 0.f) ? o.x : expm1f(o.x);
    o.y = (o.y > 0.f) ? o.y : expm1f(o.y);
    o.z = (o.z > 0.f) ? o.z : expm1f(o.z);
    o.w = (o.w > 0.f) ? o.w : expm1f(o.w);
    *(float4*)&g_h2in[(long long)gw * HC + c4] = o;
}

// ---------------- GAT layer 2 (single head, 32 ch, writes d_out) --------
__global__ void __launch_bounds__(256) k_gat2(const float* __restrict__ b2,
                                              float* __restrict__ out) {
    int gw = (blockIdx.x * 256 + threadIdx.x) >> 5;
    if (gw >= N_NODES) return;
    int lane = threadIdx.x & 31;
    int beg = g_off[gw], end = g_off[gw + 1];
    float aDn = g_aD2[gw];

    float m = -1e30f, ss = 0.f;
    for (int e = beg + lane; e < end; e += 32) {
        int s = g_csr[e];
        float l = g_aS2[s] + aDn; l = fmaxf(l, NEG_SLOPE * l);
        float nm = fmaxf(m, l);
        ss = ss * __expf(m - nm) + __expf(l - nm);
        m = nm;
    }
#pragma unroll
    for (int o = 16; o; o >>= 1) {
        float om = __shfl_xor_sync(~0u, m, o);
        float os = __shfl_xor_sync(~0u, ss, o);
        float nm = fmaxf(m, om);
        ss = ss * __expf(m - nm) + os * __expf(om - nm);
        m = nm;
    }
    float inv = 1.f / ss;

    float acc = 0.f;
    for (int e = beg; e < end; e++) {
        int s = g_csr[e];
        float l = g_aS2[s] + aDn; l = fmaxf(l, NEG_SLOPE * l);
        float w = __expf(l - m) * inv;
        acc += w * g_h2[(long long)s * OUT_CH + lane];
    }
    out[(long long)gw * OUT_CH + lane] = acc + b2[lane];
}

// ---------------- launcher ----------------
extern "C" void kernel_launch(void* const* d_in, const int* in_sizes, int n_in,
                              void* d_out, int out_size) {
    const float* x   = (const float*)d_in[0];
    const void*  ei  = d_in[1];
    const float* W1  = (const float*)d_in[2];
    const float* as1 = (const float*)d_in[3];
    const float* ad1 = (const float*)d_in[4];
    const float* b1  = (const float*)d_in[5];
    const float* W2  = (const float*)d_in[6];
    const float* as2 = (const float*)d_in[7];
    const float* ad2 = (const float*)d_in[8];
    const float* b2  = (const float*)d_in[9];
    float* out = (float*)d_out;

    float *h1p, *h2inp, *h2p;
    cudaGetSymbolAddress((void**)&h1p,   g_h1);
    cudaGetSymbolAddress((void**)&h2inp, g_h2in);
    cudaGetSymbolAddress((void**)&h2p,   g_h2);

    cudaFuncSetAttribute((const void*)k_gemm<128, 16, 4>,
                         cudaFuncAttributeMaxDynamicSharedMemorySize, 128 * 128 * 4);

    // CSR build
    k_detect<<<1, 256>>>((const int*)ei);
    k_zero<<<(N_NODES + 255) / 256, 256>>>();
    k_count<<<(E_TOT + 255) / 256, 256>>>(ei);
    k_scan1<<<(N_NODES + 1023) / 1024, 1024>>>();
    k_scan2<<<1, 1024>>>();
    k_scan3<<<(N_NODES + 255) / 256, 256>>>();
    k_scatter<<<(E_TOT + 255) / 256, 256>>>(ei);

    // layer 1
    k_gemm<128, 16, 4><<<(N_NODES + 63) / 64, 256, 128 * 128 * 4>>>(x, W1, h1p, N_NODES);
    k_alpha1<<<(N_NODES + 7) / 8, 256>>>(as1, ad1);
    k_gat1<<<(N_NODES + 7) / 8, 256>>>(b1);

    // layer 2
    k_gemm<32, 4, 4><<<(N_NODES + 255) / 256, 256, 128 * 32 * 4>>>(h2inp, W2, h2p, N_NODES);
    k_alpha2<<<(N_NODES + 7) / 8, 256>>>(as2, ad2);
    k_gat2<<<(N_NODES + 7) / 8, 256>>>(b2, out);
}

// round 2
// speedup vs baseline: 1.1733x; 1.1733x over previous
#include <cuda_runtime.h>
#include <math.h>

// ---------------- problem constants ----------------
#define N_NODES  100000
#define N_EDGES  1600000
#define E_TOT    (N_EDGES + N_NODES)   // edges + self loops
#define F_IN     128
#define HC       128                   // HEADS*HID
#define HEADS    4
#define HID      32
#define OUT_CH   32
#define NEG_SLOPE 0.2f

// ---------------- scratch (device globals; no allocation allowed) -------
__device__ float g_h1  [N_NODES * HC];      // 51.2 MB  h1 = x @ W1
__device__ float g_h2in[N_NODES * HC];      // 51.2 MB  elu(agg1 + b1)
__device__ float g_h2  [N_NODES * OUT_CH];  // 12.8 MB  h2 = h2in @ W2
__device__ float g_aS1 [N_NODES * 4];
__device__ float g_aD1 [N_NODES * 4];
__device__ float g_aS2 [N_NODES];
__device__ float g_aD2 [N_NODES];
__device__ int   g_deg [N_NODES];
__device__ int   g_off [N_NODES + 1];
__device__ int   g_cursor[N_NODES];
__device__ int   g_csr [E_TOT];             // src node per dst-sorted edge
__device__ int   g_bsum[128];
__device__ int   g_is64;

// ---------------- edge dtype detection (int64 vs int32) -----------------
__device__ __forceinline__ int edge_at(const void* e, long long idx) {
    return g_is64 ? (int)((const long long*)e)[idx] : ((const int*)e)[idx];
}

// ---------------- CSR build ----------------
// zero degree array; block 0 also detects edge dtype
__global__ void k_zero(const int* __restrict__ w) {
    int i = blockIdx.x * blockDim.x + threadIdx.x;
    if (i < N_NODES) g_deg[i] = 0;
    if (blockIdx.x == 0) {
        __shared__ int flag;
        if (threadIdx.x == 0) flag = 0;
        __syncthreads();
        int any = 0;
        for (int j = threadIdx.x; j < 2048; j += 256) any |= w[2 * j + 1];
        if (any) atomicOr(&flag, 1);
        __syncthreads();
        if (threadIdx.x == 0) g_is64 = (flag == 0) ? 1 : 0;
    }
}

__global__ void k_count(const void* __restrict__ e) {
    int t = blockIdx.x * blockDim.x + threadIdx.x;
    if (t >= E_TOT) return;
    int dst = (t < N_EDGES) ? edge_at(e, (long long)N_EDGES + t) : (t - N_EDGES);
    atomicAdd(&g_deg[dst], 1);
}

// per-block inclusive scan of g_deg -> g_off (block-local), totals -> g_bsum
__global__ void __launch_bounds__(1024) k_scan1() {
    __shared__ int wsum[32];
    int t = threadIdx.x, b = blockIdx.x;
    int i = b * 1024 + t;
    int v = (i < N_NODES) ? g_deg[i] : 0;
    int lane = t & 31, w = t >> 5;
    int s = v;
#pragma unroll
    for (int o = 1; o < 32; o <<= 1) { int u = __shfl_up_sync(~0u, s, o); if (lane >= o) s += u; }
    if (lane == 31) wsum[w] = s;
    __syncthreads();
    if (w == 0) {
        int xx = wsum[lane];
#pragma unroll
        for (int o = 1; o < 32; o <<= 1) { int u = __shfl_up_sync(~0u, xx, o); if (lane >= o) xx += u; }
        wsum[lane] = xx;
    }
    __syncthreads();
    int incl = s + (w ? wsum[w - 1] : 0);
    if (i < N_NODES) g_off[i] = incl;
    if (t == 1023) g_bsum[b] = incl;
}

// scan of 98 block totals -> exclusive
__global__ void __launch_bounds__(1024) k_scan2() {
    const int NB = (N_NODES + 1023) / 1024;  // 98
    __shared__ int wsum[32];
    int t = threadIdx.x;
    int v = (t < NB) ? g_bsum[t] : 0;
    int lane = t & 31, w = t >> 5;
    int s = v;
#pragma unroll
    for (int o = 1; o < 32; o <<= 1) { int u = __shfl_up_sync(~0u, s, o); if (lane >= o) s += u; }
    if (lane == 31) wsum[w] = s;
    __syncthreads();
    if (w == 0) {
        int xx = wsum[lane];
#pragma unroll
        for (int o = 1; o < 32; o <<= 1) { int u = __shfl_up_sync(~0u, xx, o); if (lane >= o) xx += u; }
        wsum[lane] = xx;
    }
    __syncthreads();
    int incl = s + (w ? wsum[w - 1] : 0);
    if (t < NB) g_bsum[t] = incl - v;  // exclusive
}

__global__ void k_scan3() {
    int i = blockIdx.x * blockDim.x + threadIdx.x;
    if (i >= N_NODES) return;
    int incl = g_off[i] + g_bsum[i >> 10];
    int excl = incl - g_deg[i];
    g_off[i]    = excl;
    g_cursor[i] = excl;
    if (i == N_NODES - 1) g_off[N_NODES] = incl;
}

__global__ void k_scatter(const void* __restrict__ e) {
    int t = blockIdx.x * blockDim.x + threadIdx.x;
    if (t >= E_TOT) return;
    int s, d;
    if (t < N_EDGES) { s = edge_at(e, t); d = edge_at(e, (long long)N_EDGES + t); }
    else             { s = d = t - N_EDGES; }
    int pos = atomicAdd(&g_cursor[d], 1);
    g_csr[pos] = s;
}

// ---------------- GEMM + fused alpha epilogue ----------------------------
// Y[r, 0:BN] = X[r, 0:128] @ W[128, BN]; also aS[r,h] = Y[r]·a_src[h],
// aD[r,h] = Y[r]·a_dst[h] computed from register accumulators.
// 256 threads; W fully staged in dynamic smem; A rows streamed via L1.
template <int BN, int TX, int NPT, int H>
__global__ void __launch_bounds__(256) k_gemm(const float* __restrict__ X,
                                              const float* __restrict__ Wg,
                                              float* __restrict__ Y,
                                              const float* __restrict__ As,
                                              const float* __restrict__ Ad,
                                              float* __restrict__ aSo,
                                              float* __restrict__ aDo,
                                              int nrows) {
    extern __shared__ float ws[];
    const int K = 128;
    int tid = threadIdx.x;
    for (int i = tid * 4; i < K * BN; i += 1024)
        *(float4*)(ws + i) = *(const float4*)(Wg + i);
    __syncthreads();

    const int TY = 256 / TX;
    const int BM = TY * NPT;
    int tx = tid % TX, ty = tid / TX;
    int row0 = blockIdx.x * BM + ty * NPT;

    float acc[NPT][8];
#pragma unroll
    for (int i = 0; i < NPT; i++)
#pragma unroll
        for (int j = 0; j < 8; j++) acc[i][j] = 0.f;

#pragma unroll 1
    for (int k = 0; k < K; k += 4) {
        float4 xa[NPT];
#pragma unroll
        for (int i = 0; i < NPT; i++) {
            int r = row0 + i;
            xa[i] = (r < nrows) ? *(const float4*)(X + r * K + k)
                                : make_float4(0.f, 0.f, 0.f, 0.f);
        }
#pragma unroll
        for (int kk = 0; kk < 4; kk++) {
            float4 b0 = *(const float4*)(ws + (k + kk) * BN + tx * 8);
            float4 b1 = *(const float4*)(ws + (k + kk) * BN + tx * 8 + 4);
#pragma unroll
            for (int i = 0; i < NPT; i++) {
                float a = (kk == 0) ? xa[i].x : (kk == 1) ? xa[i].y : (kk == 2) ? xa[i].z : xa[i].w;
                acc[i][0] += a * b0.x; acc[i][1] += a * b0.y;
                acc[i][2] += a * b0.z; acc[i][3] += a * b0.w;
                acc[i][4] += a * b1.x; acc[i][5] += a * b1.y;
                acc[i][6] += a * b1.z; acc[i][7] += a * b1.w;
            }
        }
    }

    // epilogue: store Y rows + fused alpha reduction.
    // channels per head C = BN/H; a thread's 8 channels live in one head
    // (8 | C). The C channels of a head span C/8 = 4 consecutive tx lanes
    // (BN/H = 32 in both instantiations) -> shfl_xor 1,2 reduces them.
    int head = (H > 1) ? (tx >> 2) : 0;
#pragma unroll
    for (int i = 0; i < NPT; i++) {
        int r = row0 + i;
        if (r >= nrows) continue;
        *(float4*)(Y + r * BN + tx * 8)     = make_float4(acc[i][0], acc[i][1], acc[i][2], acc[i][3]);
        *(float4*)(Y + r * BN + tx * 8 + 4) = make_float4(acc[i][4], acc[i][5], acc[i][6], acc[i][7]);
        float ps = 0.f, pd = 0.f;
#pragma unroll
        for (int j = 0; j < 8; j++) {
            int ch = tx * 8 + j;
            ps += acc[i][j] * __ldg(As + ch);
            pd += acc[i][j] * __ldg(Ad + ch);
        }
        ps += __shfl_xor_sync(~0u, ps, 1); pd += __shfl_xor_sync(~0u, pd, 1);
        ps += __shfl_xor_sync(~0u, ps, 2); pd += __shfl_xor_sync(~0u, pd, 2);
        if ((tx & 3) == 0) {
            aSo[r * H + head] = ps;
            aDo[r * H + head] = pd;
        }
    }
}

// ---------------- GAT layer 1: single-pass softmax-aggregate ------------
// No max subtraction: logits are O(±6), exp cannot overflow fp32.
// One warp per destination node; lane owns channels [4*lane, 4*lane+4)
// (head = lane>>3). denom is accumulated redundantly per lane (identical
// within each 8-lane head group), so no shuffle is needed at the end.
__global__ void __launch_bounds__(256) k_gat1(const float* __restrict__ b1) {
    int gw = (blockIdx.x * 256 + threadIdx.x) >> 5;
    if (gw >= N_NODES) return;
    int lane = threadIdx.x & 31;
    int beg = g_off[gw], end = g_off[gw + 1];

    int head = lane >> 3;
    int c4 = lane * 4;
    float aDh = g_aD1[gw * 4 + head];

    float4 acc = make_float4(0.f, 0.f, 0.f, 0.f);
    float denom = 0.f;

    int e = beg;
    for (; e + 4 <= end; e += 4) {
        int s0 = g_csr[e], s1 = g_csr[e + 1], s2 = g_csr[e + 2], s3 = g_csr[e + 3];
        float a0 = g_aS1[s0 * 4 + head], a1 = g_aS1[s1 * 4 + head];
        float a2 = g_aS1[s2 * 4 + head], a3 = g_aS1[s3 * 4 + head];
        float4 v0 = *(const float4*)&g_h1[s0 * HC + c4];
        float4 v1 = *(const float4*)&g_h1[s1 * HC + c4];
        float4 v2 = *(const float4*)&g_h1[s2 * HC + c4];
        float4 v3 = *(const float4*)&g_h1[s3 * HC + c4];
        float l0 = a0 + aDh; l0 = fmaxf(l0, NEG_SLOPE * l0); float w0 = __expf(l0);
        float l1 = a1 + aDh; l1 = fmaxf(l1, NEG_SLOPE * l1); float w1 = __expf(l1);
        float l2 = a2 + aDh; l2 = fmaxf(l2, NEG_SLOPE * l2); float w2 = __expf(l2);
        float l3 = a3 + aDh; l3 = fmaxf(l3, NEG_SLOPE * l3); float w3 = __expf(l3);
        denom += (w0 + w1) + (w2 + w3);
        acc.x += w0 * v0.x + w1 * v1.x + w2 * v2.x + w3 * v3.x;
        acc.y += w0 * v0.y + w1 * v1.y + w2 * v2.y + w3 * v3.y;
        acc.z += w0 * v0.z + w1 * v1.z + w2 * v2.z + w3 * v3.z;
        acc.w += w0 * v0.w + w1 * v1.w + w2 * v2.w + w3 * v3.w;
    }
    for (; e < end; e++) {
        int s = g_csr[e];
        float a = g_aS1[s * 4 + head];
        float l = a + aDh; l = fmaxf(l, NEG_SLOPE * l);
        float w = __expf(l);
        float4 v = *(const float4*)&g_h1[s * HC + c4];
        denom += w;
        acc.x += w * v.x; acc.y += w * v.y; acc.z += w * v.z; acc.w += w * v.w;
    }

    float inv = 1.f / denom;
    float4 bb = *(const float4*)&b1[c4];
    float4 o;
    o.x = acc.x * inv + bb.x; o.y = acc.y * inv + bb.y;
    o.z = acc.z * inv + bb.z; o.w = acc.w * inv + bb.w;
    o.x = (o.x > 0.f) ? o.x : expm1f(o.x);
    o.y = (o.y > 0.f) ? o.y : expm1f(o.y);
    o.z = (o.z > 0.f) ? o.z : expm1f(o.z);
    o.w = (o.w > 0.f) ? o.w : expm1f(o.w);
    *(float4*)&g_h2in[gw * HC + c4] = o;
}

// ---------------- GAT layer 2 (single head, 32 ch, writes d_out) --------
__global__ void __launch_bounds__(256) k_gat2(const float* __restrict__ b2,
                                              float* __restrict__ out) {
    int gw = (blockIdx.x * 256 + threadIdx.x) >> 5;
    if (gw >= N_NODES) return;
    int lane = threadIdx.x & 31;
    int beg = g_off[gw], end = g_off[gw + 1];
    float aDn = g_aD2[gw];

    float acc = 0.f, denom = 0.f;
    int e = beg;
    for (; e + 4 <= end; e += 4) {
        int s0 = g_csr[e], s1 = g_csr[e + 1], s2 = g_csr[e + 2], s3 = g_csr[e + 3];
        float a0 = g_aS2[s0], a1 = g_aS2[s1], a2 = g_aS2[s2], a3 = g_aS2[s3];
        float v0 = g_h2[s0 * OUT_CH + lane];
        float v1 = g_h2[s1 * OUT_CH + lane];
        float v2 = g_h2[s2 * OUT_CH + lane];
        float v3 = g_h2[s3 * OUT_CH + lane];
        float l0 = a0 + aDn; l0 = fmaxf(l0, NEG_SLOPE * l0); float w0 = __expf(l0);
        float l1 = a1 + aDn; l1 = fmaxf(l1, NEG_SLOPE * l1); float w1 = __expf(l1);
        float l2 = a2 + aDn; l2 = fmaxf(l2, NEG_SLOPE * l2); float w2 = __expf(l2);
        float l3 = a3 + aDn; l3 = fmaxf(l3, NEG_SLOPE * l3); float w3 = __expf(l3);
        denom += (w0 + w1) + (w2 + w3);
        acc += w0 * v0 + w1 * v1 + w2 * v2 + w3 * v3;
    }
    for (; e < end; e++) {
        int s = g_csr[e];
        float l = g_aS2[s] + aDn; l = fmaxf(l, NEG_SLOPE * l);
        float w = __expf(l);
        denom += w;
        acc += w * g_h2[s * OUT_CH + lane];
    }
    out[gw * OUT_CH + lane] = acc / denom + b2[lane];
}

// ---------------- launcher ----------------
extern "C" void kernel_launch(void* const* d_in, const int* in_sizes, int n_in,
                              void* d_out, int out_size) {
    const float* x   = (const float*)d_in[0];
    const void*  ei  = d_in[1];
    const float* W1  = (const float*)d_in[2];
    const float* as1 = (const float*)d_in[3];
    const float* ad1 = (const float*)d_in[4];
    const float* b1  = (const float*)d_in[5];
    const float* W2  = (const float*)d_in[6];
    const float* as2 = (const float*)d_in[7];
    const float* ad2 = (const float*)d_in[8];
    const float* b2  = (const float*)d_in[9];
    float* out = (float*)d_out;

    float *h1p, *h2inp, *h2p, *aS1p, *aD1p, *aS2p, *aD2p;
    cudaGetSymbolAddress((void**)&h1p,   g_h1);
    cudaGetSymbolAddress((void**)&h2inp, g_h2in);
    cudaGetSymbolAddress((void**)&h2p,   g_h2);
    cudaGetSymbolAddress((void**)&aS1p,  g_aS1);
    cudaGetSymbolAddress((void**)&aD1p,  g_aD1);
    cudaGetSymbolAddress((void**)&aS2p,  g_aS2);
    cudaGetSymbolAddress((void**)&aD2p,  g_aD2);

    cudaFuncSetAttribute((const void*)k_gemm<128, 16, 4, 4>,
                         cudaFuncAttributeMaxDynamicSharedMemorySize, 128 * 128 * 4);

    // CSR build
    k_zero<<<(N_NODES + 255) / 256, 256>>>((const int*)ei);
    k_count<<<(E_TOT + 255) / 256, 256>>>(ei);
    k_scan1<<<(N_NODES + 1023) / 1024, 1024>>>();
    k_scan2<<<1, 1024>>>();
    k_scan3<<<(N_NODES + 255) / 256, 256>>>();
    k_scatter<<<(E_TOT + 255) / 256, 256>>>(ei);

    // layer 1: GEMM (+alpha epilogue), then fused softmax-aggregate
    k_gemm<128, 16, 4, 4><<<(N_NODES + 63) / 64, 256, 128 * 128 * 4>>>(
        x, W1, h1p, as1, ad1, aS1p, aD1p, N_NODES);
    k_gat1<<<(N_NODES + 7) / 8, 256>>>(b1);

    // layer 2
    k_gemm<32, 4, 4, 1><<<(N_NODES + 255) / 256, 256, 128 * 32 * 4>>>(
        h2inp, W2, h2p, as2, ad2, aS2p, aD2p, N_NODES);
    k_gat2<<<(N_NODES + 7) / 8, 256>>>(b2, out);
}

// round 4
// speedup vs baseline: 1.2741x; 1.0859x over previous
#include <cuda_runtime.h>
#include <math.h>

// ---------------- problem constants ----------------
#define N_NODES  100000
#define N_EDGES  1600000
#define E_TOT    (N_EDGES + N_NODES)   // edges + self loops
#define F_IN     128
#define HC       128                   // HEADS*HID
#define HEADS    4
#define HID      32
#define OUT_CH   32
#define NEG_SLOPE 0.2f

// ---------------- scratch (device globals; no allocation allowed) -------
__device__ float g_h1  [N_NODES * HC];      // 51.2 MB  h1 = x @ W1
__device__ float g_h2in[N_NODES * HC];      // 51.2 MB  elu(agg1 + b1)
__device__ float g_h2  [N_NODES * OUT_CH];  // 12.8 MB  h2 = h2in @ W2
__device__ float g_aS1 [N_NODES * 4];
__device__ float g_aD1 [N_NODES * 4];
__device__ float g_aS2 [N_NODES];
__device__ float g_aD2 [N_NODES];
__device__ int   g_deg [N_NODES];
__device__ int   g_off [N_NODES + 1];
__device__ int   g_cursor[N_NODES];
__device__ int   g_csr [E_TOT];             // src node per dst-sorted edge
__device__ int   g_bsum[128];
__device__ int   g_is64;

// ---------------- packed f32x2 helpers (Blackwell FFMA2) ----------------
__device__ __forceinline__ unsigned long long pack2(float x, float y) {
    unsigned long long r;
    asm("mov.b64 %0, {%1, %2};" : "=l"(r) : "f"(x), "f"(y));
    return r;
}
__device__ __forceinline__ void unpack2(unsigned long long v, float& x, float& y) {
    asm("mov.b64 {%0, %1}, %2;" : "=f"(x), "=f"(y) : "l"(v));
}
__device__ __forceinline__ void ffma2(unsigned long long& d, unsigned long long a,
                                      unsigned long long b) {
    asm("fma.rn.f32x2 %0, %1, %2, %0;" : "+l"(d) : "l"(a), "l"(b));
}

// ---------------- edge dtype detection (int64 vs int32) -----------------
__device__ __forceinline__ int edge_at(const void* e, long long idx) {
    return g_is64 ? (int)((const long long*)e)[idx] : ((const int*)e)[idx];
}

// ---------------- CSR build ----------------
// zero degree array; block 0 also detects edge dtype
__global__ void k_zero(const int* __restrict__ w) {
    int i = blockIdx.x * blockDim.x + threadIdx.x;
    if (i < N_NODES) g_deg[i] = 0;
    if (blockIdx.x == 0) {
        __shared__ int flag;
        if (threadIdx.x == 0) flag = 0;
        __syncthreads();
        int any = 0;
        for (int j = threadIdx.x; j < 2048; j += 256) any |= w[2 * j + 1];
        if (any) atomicOr(&flag, 1);
        __syncthreads();
        if (threadIdx.x == 0) g_is64 = (flag == 0) ? 1 : 0;
    }
}

__global__ void k_count(const void* __restrict__ e) {
    int t = blockIdx.x * blockDim.x + threadIdx.x;
    if (t >= E_TOT) return;
    int dst = (t < N_EDGES) ? edge_at(e, (long long)N_EDGES + t) : (t - N_EDGES);
    atomicAdd(&g_deg[dst], 1);
}

// per-block inclusive scan of g_deg -> g_off (block-local), totals -> g_bsum
__global__ void __launch_bounds__(1024) k_scan1() {
    __shared__ int wsum[32];
    int t = threadIdx.x, b = blockIdx.x;
    int i = b * 1024 + t;
    int v = (i < N_NODES) ? g_deg[i] : 0;
    int lane = t & 31, w = t >> 5;
    int s = v;
#pragma unroll
    for (int o = 1; o < 32; o <<= 1) { int u = __shfl_up_sync(~0u, s, o); if (lane >= o) s += u; }
    if (lane == 31) wsum[w] = s;
    __syncthreads();
    if (w == 0) {
        int xx = wsum[lane];
#pragma unroll
        for (int o = 1; o < 32; o <<= 1) { int u = __shfl_up_sync(~0u, xx, o); if (lane >= o) xx += u; }
        wsum[lane] = xx;
    }
    __syncthreads();
    int incl = s + (w ? wsum[w - 1] : 0);
    if (i < N_NODES) g_off[i] = incl;
    if (t == 1023) g_bsum[b] = incl;
}

// scan of 98 block totals -> exclusive
__global__ void __launch_bounds__(1024) k_scan2() {
    const int NB = (N_NODES + 1023) / 1024;  // 98
    __shared__ int wsum[32];
    int t = threadIdx.x;
    int v = (t < NB) ? g_bsum[t] : 0;
    int lane = t & 31, w = t >> 5;
    int s = v;
#pragma unroll
    for (int o = 1; o < 32; o <<= 1) { int u = __shfl_up_sync(~0u, s, o); if (lane >= o) s += u; }
    if (lane == 31) wsum[w] = s;
    __syncthreads();
    if (w == 0) {
        int xx = wsum[lane];
#pragma unroll
        for (int o = 1; o < 32; o <<= 1) { int u = __shfl_up_sync(~0u, xx, o); if (lane >= o) xx += u; }
        wsum[lane] = xx;
    }
    __syncthreads();
    int incl = s + (w ? wsum[w - 1] : 0);
    if (t < NB) g_bsum[t] = incl - v;  // exclusive
}

__global__ void k_scan3() {
    int i = blockIdx.x * blockDim.x + threadIdx.x;
    if (i >= N_NODES) return;
    int incl = g_off[i] + g_bsum[i >> 10];
    int excl = incl - g_deg[i];
    g_off[i]    = excl;
    g_cursor[i] = excl;
    if (i == N_NODES - 1) g_off[N_NODES] = incl;
}

__global__ void k_scatter(const void* __restrict__ e) {
    int t = blockIdx.x * blockDim.x + threadIdx.x;
    if (t >= E_TOT) return;
    int s, d;
    if (t < N_EDGES) { s = edge_at(e, t); d = edge_at(e, (long long)N_EDGES + t); }
    else             { s = d = t - N_EDGES; }
    int pos = atomicAdd(&g_cursor[d], 1);
    g_csr[pos] = s;
}

// ---------------- GEMM (FFMA2) + fused alpha epilogue --------------------
// Y[r, 0:BN] = X[r, 0:128] @ W[128, BN]; also aS[r,h] = Y[r]·a_src[h],
// aD[r,h] = Y[r]·a_dst[h] from register accumulators.
// 256 threads; W fully staged in dynamic smem; A rows streamed via L1.
// Each thread: NPT rows x 8 cols, accumulated as 4 packed f32x2 per row.
template <int BN, int TX, int NPT, int H>
__global__ void __launch_bounds__(256) k_gemm(const float* __restrict__ X,
                                              const float* __restrict__ Wg,
                                              float* __restrict__ Y,
                                              const float* __restrict__ As,
                                              const float* __restrict__ Ad,
                                              float* __restrict__ aSo,
                                              float* __restrict__ aDo,
                                              int nrows) {
    extern __shared__ float ws[];
    const int K = 128;
    int tid = threadIdx.x;
    for (int i = tid * 4; i < K * BN; i += 1024)
        *(float4*)(ws + i) = *(const float4*)(Wg + i);
    __syncthreads();

    const int TY = 256 / TX;
    const int BM = TY * NPT;
    int tx = tid % TX, ty = tid / TX;
    int row0 = blockIdx.x * BM + ty * NPT;

    unsigned long long acc[NPT][4];
#pragma unroll
    for (int i = 0; i < NPT; i++)
#pragma unroll
        for (int j = 0; j < 4; j++) acc[i][j] = 0ULL;

#pragma unroll 1
    for (int k = 0; k < K; k += 4) {
        float4 xa[NPT];
#pragma unroll
        for (int i = 0; i < NPT; i++) {
            int r = row0 + i;
            xa[i] = (r < nrows) ? *(const float4*)(X + r * K + k)
                                : make_float4(0.f, 0.f, 0.f, 0.f);
        }
#pragma unroll
        for (int kk = 0; kk < 4; kk++) {
            const float* bp = ws + (k + kk) * BN + tx * 8;
            ulonglong2 B0 = *(const ulonglong2*)(bp);
            ulonglong2 B1 = *(const ulonglong2*)(bp + 4);
#pragma unroll
            for (int i = 0; i < NPT; i++) {
                float a = (kk == 0) ? xa[i].x : (kk == 1) ? xa[i].y : (kk == 2) ? xa[i].z : xa[i].w;
                unsigned long long aa = pack2(a, a);
                ffma2(acc[i][0], aa, B0.x);
                ffma2(acc[i][1], aa, B0.y);
                ffma2(acc[i][2], aa, B1.x);
                ffma2(acc[i][3], aa, B1.y);
            }
        }
    }

    // epilogue: store Y rows + fused alpha reduction.
    // A thread's 8 channels live in one head (head = tx>>2 when H>1);
    // the head's 32 channels span 4 consecutive tx lanes -> shfl_xor 1,2.
    int head = (H > 1) ? (tx >> 2) : 0;
#pragma unroll
    for (int i = 0; i < NPT; i++) {
        int r = row0 + i;
        if (r >= nrows) continue;
        float c[8];
        unpack2(acc[i][0], c[0], c[1]);
        unpack2(acc[i][1], c[2], c[3]);
        unpack2(acc[i][2], c[4], c[5]);
        unpack2(acc[i][3], c[6], c[7]);
        *(float4*)(Y + r * BN + tx * 8)     = make_float4(c[0], c[1], c[2], c[3]);
        *(float4*)(Y + r * BN + tx * 8 + 4) = make_float4(c[4], c[5], c[6], c[7]);
        float ps = 0.f, pd = 0.f;
#pragma unroll
        for (int j = 0; j < 8; j++) {
            int ch = tx * 8 + j;
            ps += c[j] * __ldg(As + ch);
            pd += c[j] * __ldg(Ad + ch);
        }
        ps += __shfl_xor_sync(~0u, ps, 1); pd += __shfl_xor_sync(~0u, pd, 1);
        ps += __shfl_xor_sync(~0u, ps, 2); pd += __shfl_xor_sync(~0u, pd, 2);
        if ((tx & 3) == 0) {
            aSo[r * H + head] = ps;
            aDo[r * H + head] = pd;
        }
    }
}

// ---------------- GAT layer 1: single-pass softmax-aggregate ------------
// No max subtraction: logits are O(±6), exp cannot overflow fp32.
// One warp per destination node; lane owns channels [4*lane, 4*lane+4)
// (head = lane>>3). denom accumulated redundantly per lane.
__global__ void __launch_bounds__(256) k_gat1(const float* __restrict__ b1) {
    int gw = (blockIdx.x * 256 + threadIdx.x) >> 5;
    if (gw >= N_NODES) return;
    int lane = threadIdx.x & 31;
    int beg = g_off[gw], end = g_off[gw + 1];

    int head = lane >> 3;
    int c4 = lane * 4;
    float aDh = g_aD1[gw * 4 + head];

    float4 acc = make_float4(0.f, 0.f, 0.f, 0.f);
    float denom = 0.f;

    int e = beg;
    for (; e + 4 <= end; e += 4) {
        int s0 = g_csr[e], s1 = g_csr[e + 1], s2 = g_csr[e + 2], s3 = g_csr[e + 3];
        float a0 = g_aS1[s0 * 4 + head], a1 = g_aS1[s1 * 4 + head];
        float a2 = g_aS1[s2 * 4 + head], a3 = g_aS1[s3 * 4 + head];
        float4 v0 = *(const float4*)&g_h1[s0 * HC + c4];
        float4 v1 = *(const float4*)&g_h1[s1 * HC + c4];
        float4 v2 = *(const float4*)&g_h1[s2 * HC + c4];
        float4 v3 = *(const float4*)&g_h1[s3 * HC + c4];
        float l0 = a0 + aDh; l0 = fmaxf(l0, NEG_SLOPE * l0); float w0 = __expf(l0);
        float l1 = a1 + aDh; l1 = fmaxf(l1, NEG_SLOPE * l1); float w1 = __expf(l1);
        float l2 = a2 + aDh; l2 = fmaxf(l2, NEG_SLOPE * l2); float w2 = __expf(l2);
        float l3 = a3 + aDh; l3 = fmaxf(l3, NEG_SLOPE * l3); float w3 = __expf(l3);
        denom += (w0 + w1) + (w2 + w3);
        acc.x += w0 * v0.x + w1 * v1.x + w2 * v2.x + w3 * v3.x;
        acc.y += w0 * v0.y + w1 * v1.y + w2 * v2.y + w3 * v3.y;
        acc.z += w0 * v0.z + w1 * v1.z + w2 * v2.z + w3 * v3.z;
        acc.w += w0 * v0.w + w1 * v1.w + w2 * v2.w + w3 * v3.w;
    }
    for (; e < end; e++) {
        int s = g_csr[e];
        float a = g_aS1[s * 4 + head];
        float l = a + aDh; l = fmaxf(l, NEG_SLOPE * l);
        float w = __expf(l);
        float4 v = *(const float4*)&g_h1[s * HC + c4];
        denom += w;
        acc.x += w * v.x; acc.y += w * v.y; acc.z += w * v.z; acc.w += w * v.w;
    }

    float inv = 1.f / denom;
    float4 bb = *(const float4*)&b1[c4];
    float4 o;
    o.x = acc.x * inv + bb.x; o.y = acc.y * inv + bb.y;
    o.z = acc.z * inv + bb.z; o.w = acc.w * inv + bb.w;
    o.x = (o.x > 0.f) ? o.x : expm1f(o.x);
    o.y = (o.y > 0.f) ? o.y : expm1f(o.y);
    o.z = (o.z > 0.f) ? o.z : expm1f(o.z);
    o.w = (o.w > 0.f) ? o.w : expm1f(o.w);
    *(float4*)&g_h2in[gw * HC + c4] = o;
}

// ---------------- GAT layer 2 (single head, 32 ch, writes d_out) --------
__global__ void __launch_bounds__(256) k_gat2(const float* __restrict__ b2,
                                              float* __restrict__ out) {
    int gw = (blockIdx.x * 256 + threadIdx.x) >> 5;
    if (gw >= N_NODES) return;
    int lane = threadIdx.x & 31;
    int beg = g_off[gw], end = g_off[gw + 1];
    float aDn = g_aD2[gw];

    float acc = 0.f, denom = 0.f;
    int e = beg;
    for (; e + 4 <= end; e += 4) {
        int s0 = g_csr[e], s1 = g_csr[e + 1], s2 = g_csr[e + 2], s3 = g_csr[e + 3];
        float a0 = g_aS2[s0], a1 = g_aS2[s1], a2 = g_aS2[s2], a3 = g_aS2[s3];
        float v0 = g_h2[s0 * OUT_CH + lane];
        float v1 = g_h2[s1 * OUT_CH + lane];
        float v2 = g_h2[s2 * OUT_CH + lane];
        float v3 = g_h2[s3 * OUT_CH + lane];
        float l0 = a0 + aDn; l0 = fmaxf(l0, NEG_SLOPE * l0); float w0 = __expf(l0);
        float l1 = a1 + aDn; l1 = fmaxf(l1, NEG_SLOPE * l1); float w1 = __expf(l1);
        float l2 = a2 + aDn; l2 = fmaxf(l2, NEG_SLOPE * l2); float w2 = __expf(l2);
        float l3 = a3 + aDn; l3 = fmaxf(l3, NEG_SLOPE * l3); float w3 = __expf(l3);
        denom += (w0 + w1) + (w2 + w3);
        acc += w0 * v0 + w1 * v1 + w2 * v2 + w3 * v3;
    }
    for (; e < end; e++) {
        int s = g_csr[e];
        float l = g_aS2[s] + aDn; l = fmaxf(l, NEG_SLOPE * l);
        float w = __expf(l);
        denom += w;
        acc += w * g_h2[s * OUT_CH + lane];
    }
    out[gw * OUT_CH + lane] = acc / denom + b2[lane];
}

// ---------------- launcher ----------------
extern "C" void kernel_launch(void* const* d_in, const int* in_sizes, int n_in,
                              void* d_out, int out_size) {
    const float* x   = (const float*)d_in[0];
    const void*  ei  = d_in[1];
    const float* W1  = (const float*)d_in[2];
    const float* as1 = (const float*)d_in[3];
    const float* ad1 = (const float*)d_in[4];
    const float* b1  = (const float*)d_in[5];
    const float* W2  = (const float*)d_in[6];
    const float* as2 = (const float*)d_in[7];
    const float* ad2 = (const float*)d_in[8];
    const float* b2  = (const float*)d_in[9];
    float* out = (float*)d_out;

    float *h1p, *h2inp, *h2p, *aS1p, *aD1p, *aS2p, *aD2p;
    cudaGetSymbolAddress((void**)&h1p,   g_h1);
    cudaGetSymbolAddress((void**)&h2inp, g_h2in);
    cudaGetSymbolAddress((void**)&h2p,   g_h2);
    cudaGetSymbolAddress((void**)&aS1p,  g_aS1);
    cudaGetSymbolAddress((void**)&aD1p,  g_aD1);
    cudaGetSymbolAddress((void**)&aS2p,  g_aS2);
    cudaGetSymbolAddress((void**)&aD2p,  g_aD2);

    cudaFuncSetAttribute((const void*)k_gemm<128, 16, 8, 4>,
                         cudaFuncAttributeMaxDynamicSharedMemorySize, 128 * 128 * 4);

    // CSR build
    k_zero<<<(N_NODES + 255) / 256, 256>>>((const int*)ei);
    k_count<<<(E_TOT + 255) / 256, 256>>>(ei);
    k_scan1<<<(N_NODES + 1023) / 1024, 1024>>>();
    k_scan2<<<1, 1024>>>();
    k_scan3<<<(N_NODES + 255) / 256, 256>>>();
    k_scatter<<<(E_TOT + 255) / 256, 256>>>(ei);

    // layer 1: GEMM (+alpha epilogue), then fused softmax-aggregate
    k_gemm<128, 16, 8, 4><<<(N_NODES + 127) / 128, 256, 128 * 128 * 4>>>(
        x, W1, h1p, as1, ad1, aS1p, aD1p, N_NODES);
    k_gat1<<<(N_NODES + 7) / 8, 256>>>(b1);

    // layer 2
    k_gemm<32, 4, 8, 1><<<(N_NODES + 511) / 512, 256, 128 * 32 * 4>>>(
        h2inp, W2, h2p, as2, ad2, aS2p, aD2p, N_NODES);
    k_gat2<<<(N_NODES + 7) / 8, 256>>>(b2, out);
}